// round 6
// baseline (speedup 1.0000x reference)
#include <cuda_runtime.h>
#include <cuda_bf16.h>
#include <stdint.h>
#include <math.h>

#define BB 4
#define LL 2048
#define DMODEL 1024
#define DINPROJ 2336
#define HIN 1056
#define HOUT 40
#define CONVDIM 1280
#define NROWS (BB*LL)          // 8192
#define NCHUNK 16
#define CHLEN 128
#define KSPLIT 3072            // 3 * DMODEL (bf16 hi/lo split concatenated K)

// ---------------- scratch ----------------
__device__ float g_zxbcdt[NROWS * DINPROJ];
__device__ float g_udt[NROWS * HIN];
__device__ float g_cs[BB * NCHUNK * DMODEL];
__device__ float g_hb[NROWS * HOUT];
__device__ float g_dt[NROWS * 16];
__device__ float g_decay[NROWS * 16];
__device__ float g_conv[NROWS * CONVDIM];
__device__ float g_y[NROWS * DMODEL];    // scan partial (n-half 0, incl. D*x)
__device__ float g_y2[NROWS * DMODEL];   // scan partial (n-half 1)
__device__ __nv_bfloat16 g_abig[(size_t)NROWS * KSPLIT];
__device__ __nv_bfloat16 g_wbig[(size_t)DINPROJ * KSPLIT];

// ---------------- ptx helpers ----------------
__device__ __forceinline__ void cpa16(uint32_t dst, const void* src, bool v) {
    asm volatile("cp.async.cg.shared.global [%0], [%1], 16, %2;\n"
                 :: "r"(dst), "l"(src), "r"(v ? 16 : 0));
}
#define CP_COMMIT() asm volatile("cp.async.commit_group;\n")
#define CP_WAIT1()  asm volatile("cp.async.wait_group 1;\n")
__device__ __forceinline__ void ldsm4(uint32_t addr, unsigned& a0, unsigned& a1,
                                      unsigned& a2, unsigned& a3) {
    asm volatile("ldmatrix.sync.aligned.m8n8.x4.shared.b16 {%0,%1,%2,%3}, [%4];\n"
                 : "=r"(a0), "=r"(a1), "=r"(a2), "=r"(a3) : "r"(addr));
}

// ---------------- bf16 split conversion ----------------
__global__ void split3_kernel(const float* __restrict__ src, __nv_bfloat16* __restrict__ dst,
                              int rows, int mode)
{
    int idx = blockIdx.x * 256 + threadIdx.x;
    if (idx >= rows * 256) return;
    int r = idx >> 8;
    int c4 = (idx & 255) * 4;
    float4 v = *(const float4*)(src + (size_t)r * DMODEL + c4);
    __nv_bfloat16 h0 = __float2bfloat16(v.x), h1 = __float2bfloat16(v.y);
    __nv_bfloat16 h2 = __float2bfloat16(v.z), h3 = __float2bfloat16(v.w);
    __nv_bfloat16 l0 = __float2bfloat16(v.x - __bfloat162float(h0));
    __nv_bfloat16 l1 = __float2bfloat16(v.y - __bfloat162float(h1));
    __nv_bfloat16 l2 = __float2bfloat16(v.z - __bfloat162float(h2));
    __nv_bfloat16 l3 = __float2bfloat16(v.w - __bfloat162float(h3));
    __nv_bfloat162 hA = __nv_bfloat162(h0, h1), hB = __nv_bfloat162(h2, h3);
    __nv_bfloat162 lA = __nv_bfloat162(l0, l1), lB = __nv_bfloat162(l2, l3);
    __nv_bfloat162* d0 = (__nv_bfloat162*)(dst + (size_t)r * KSPLIT + c4);
    __nv_bfloat162* d1 = (__nv_bfloat162*)(dst + (size_t)r * KSPLIT + 1024 + c4);
    __nv_bfloat162* d2 = (__nv_bfloat162*)(dst + (size_t)r * KSPLIT + 2048 + c4);
    d0[0] = hA; d0[1] = hB;
    if (mode == 0) { d1[0] = hA; d1[1] = hB; d2[0] = lA; d2[1] = lB; }
    else           { d1[0] = lA; d1[1] = lB; d2[0] = hA; d2[1] = hB; }
}

// ---------------- bf16 tensor-core GEMM, 3-stage cp.async pipeline ----------------
// C[M,N] = A[M,K] * W[N,K]^T.  CTA 128x128, BK=32, 8 warps (2x4), warp 64x32.
// smem: 3 stages x (A 128x40 + W 128x40) bf16 = 3 x 20480 B = 61440 B (dynamic).
#define SSTAGE 20480
#define TGSMEM (3 * SSTAGE)

__global__ __launch_bounds__(256) void bgemm3(
    const __nv_bfloat16* __restrict__ A, const __nv_bfloat16* __restrict__ W,
    float* __restrict__ C, int M, int N, int K)
{
    extern __shared__ __align__(16) char smembuf[];
    const int bm = blockIdx.y * 128;
    const int bn = blockIdx.x * 128;
    const int tid = threadIdx.x;
    const int warp = tid >> 5;
    const int lane = tid & 31;
    const int wm = (warp >> 2) * 64;
    const int wn = (warp & 3) * 32;
    const int lq = lane >> 2;
    const int ls = lane & 3;

    const int r0 = tid >> 2;          // 0..63
    const int c0 = tid & 3;           // 16B chunk

    float acc[4][4][4];
#pragma unroll
    for (int i = 0; i < 4; i++)
#pragma unroll
        for (int j = 0; j < 4; j++)
#pragma unroll
            for (int q = 0; q < 4; q++) acc[i][j][q] = 0.f;

    const __nv_bfloat16* Ap0 = A + (size_t)(bm + r0) * K + c0 * 8;
    const __nv_bfloat16* Ap1 = Ap0 + (size_t)64 * K;
    const bool wv0 = (bn + r0) < N;
    const bool wv1 = (bn + r0 + 64) < N;
    const __nv_bfloat16* Wp0 = W + (size_t)(bn + r0) * K + c0 * 8;
    const __nv_bfloat16* Wp1 = Wp0 + (size_t)64 * K;

    // per-stage smem write addresses (byte offsets: row*80 + c0*16)
    const uint32_t sbase = (uint32_t)__cvta_generic_to_shared(smembuf);
    const uint32_t wrA0 = sbase + (uint32_t)r0 * 80 + (uint32_t)c0 * 16;
    const uint32_t wrA1 = wrA0 + 64 * 80;
    const uint32_t wrW0 = wrA0 + 10240;
    const uint32_t wrW1 = wrA1 + 10240;

    // ldmatrix addressing pattern
    const int arow = lane & 15;
    const int acol = (lane >> 4) * 8;
    const int brow = (lane & 7) + ((lane >> 4) << 3);
    const int bcol = ((lane >> 3) & 1) * 8;
    const uint32_t ldA = sbase + (uint32_t)(wm + arow) * 80 + (uint32_t)acol * 2;
    const uint32_t ldB = sbase + 10240 + (uint32_t)(wn + brow) * 80 + (uint32_t)bcol * 2;

    const int KT = K >> 5;

    // prologue: issue stages 0 and 1
#pragma unroll
    for (int ps = 0; ps < 2; ps++) {
        const int ko = ps * 32;
        const uint32_t so = (uint32_t)ps * SSTAGE;
        cpa16(wrA0 + so, Ap0 + ko, true);
        cpa16(wrA1 + so, Ap1 + ko, true);
        cpa16(wrW0 + so, Wp0 + ko, wv0);
        cpa16(wrW1 + so, Wp1 + ko, wv1);
        CP_COMMIT();
    }

    int sidx = 0;   // stage of tile kt
    int widx = 2;   // stage to write tile kt+2
    for (int kt = 0; kt < KT; kt++) {
        CP_WAIT1();           // tile kt resident (<=1 group pending)
        __syncthreads();      // also protects overwrite of stage widx (read at kt-1)

        const int nk = (kt + 2) * 32;
        if (nk < K) {
            const uint32_t so = (uint32_t)widx * SSTAGE;
            cpa16(wrA0 + so, Ap0 + nk, true);
            cpa16(wrA1 + so, Ap1 + nk, true);
            cpa16(wrW0 + so, Wp0 + nk, wv0);
            cpa16(wrW1 + so, Wp1 + nk, wv1);
        }
        CP_COMMIT();          // commit (possibly empty) to keep group accounting

        const uint32_t so = (uint32_t)sidx * SSTAGE;
#pragma unroll
        for (int ks = 0; ks < 2; ks++) {
            const uint32_t kko = (uint32_t)(ks * 32);   // 16 bf16 = 32 bytes
            unsigned a[4][4], b[2][4];
#pragma unroll
            for (int i = 0; i < 4; i++)
                ldsm4(ldA + so + kko + (uint32_t)(i * 16) * 80,
                      a[i][0], a[i][1], a[i][2], a[i][3]);
#pragma unroll
            for (int jp = 0; jp < 2; jp++)
                ldsm4(ldB + so + kko + (uint32_t)(jp * 16) * 80,
                      b[jp][0], b[jp][1], b[jp][2], b[jp][3]);
#pragma unroll
            for (int i = 0; i < 4; i++)
#pragma unroll
                for (int j = 0; j < 4; j++) {
                    const unsigned b0 = b[j >> 1][(j & 1) * 2];
                    const unsigned b1 = b[j >> 1][(j & 1) * 2 + 1];
                    asm volatile(
                        "mma.sync.aligned.m16n8k16.row.col.f32.bf16.bf16.f32 "
                        "{%0,%1,%2,%3}, {%4,%5,%6,%7}, {%8,%9}, {%0,%1,%2,%3};\n"
                        : "+f"(acc[i][j][0]), "+f"(acc[i][j][1]),
                          "+f"(acc[i][j][2]), "+f"(acc[i][j][3])
                        : "r"(a[i][0]), "r"(a[i][1]), "r"(a[i][2]), "r"(a[i][3]),
                          "r"(b0), "r"(b1));
                }
        }
        sidx = (sidx == 2) ? 0 : sidx + 1;
        widx = (widx == 2) ? 0 : widx + 1;
    }

#pragma unroll
    for (int i = 0; i < 4; i++) {
        const int r = bm + wm + i * 16 + lq;
#pragma unroll
        for (int j = 0; j < 4; j++) {
            const int n = bn + wn + j * 8 + 2 * ls;
            if (n < N) {
                *(float2*)&C[(size_t)r * N + n]       = make_float2(acc[i][j][0], acc[i][j][1]);
                *(float2*)&C[(size_t)(r + 8) * N + n] = make_float2(acc[i][j][2], acc[i][j][3]);
            }
        }
    }
}

// ---------------- fp32 h_proj GEMM: BM=64, BN=64 (N=40 guarded), BK=16 ----------------
__global__ __launch_bounds__(256) void sgemm64(
    const float* __restrict__ A, const float* __restrict__ W,
    float* __restrict__ C, int M, int N, int K)
{
    __shared__ __align__(16) float As[16][64];
    __shared__ __align__(16) float Bs[16][64];
    const int bm = blockIdx.y * 64;
    const int tid = threadIdx.x;
    const int lr = tid >> 2;
    const int lc = (tid & 3) << 2;
    const int tr = tid >> 4;
    const int tc = tid & 15;

    float acc[4][4];
#pragma unroll
    for (int i = 0; i < 4; i++)
#pragma unroll
        for (int j = 0; j < 4; j++) acc[i][j] = 0.f;

    const float* Aptr = A + (size_t)(bm + lr) * K + lc;
    const float* Wptr = W + (size_t)lr * K + lc;
    const bool wvalid = lr < N;

    for (int k0 = 0; k0 < K; k0 += 16) {
        float4 av = *(const float4*)(Aptr + k0);
        float4 bv = wvalid ? *(const float4*)(Wptr + k0) : make_float4(0.f, 0.f, 0.f, 0.f);
        As[lc + 0][lr] = av.x; As[lc + 1][lr] = av.y; As[lc + 2][lr] = av.z; As[lc + 3][lr] = av.w;
        Bs[lc + 0][lr] = bv.x; Bs[lc + 1][lr] = bv.y; Bs[lc + 2][lr] = bv.z; Bs[lc + 3][lr] = bv.w;
        __syncthreads();
#pragma unroll
        for (int k = 0; k < 16; k++) {
            float ra[4], rb[4];
#pragma unroll
            for (int i = 0; i < 4; i++) ra[i] = As[k][tr + 16 * i];
#pragma unroll
            for (int j = 0; j < 4; j++) rb[j] = Bs[k][tc + 16 * j];
#pragma unroll
            for (int i = 0; i < 4; i++)
#pragma unroll
                for (int j = 0; j < 4; j++) acc[i][j] = fmaf(ra[i], rb[j], acc[i][j]);
        }
        __syncthreads();
    }
#pragma unroll
    for (int i = 0; i < 4; i++) {
        const int m = bm + tr + 16 * i;
#pragma unroll
        for (int j = 0; j < 4; j++) {
            const int n = tc + 16 * j;
            if (n < N) C[(size_t)m * N + n] = acc[i][j];
        }
    }
}

// ---------------- spectral residual ----------------
__global__ void chunksum_kernel(const float* __restrict__ u)
{
    const int b = blockIdx.x >> 4;
    const int c = blockIdx.x & 15;
    const int d = threadIdx.x;
    const float* up = u + ((size_t)b * LL + (size_t)c * CHLEN) * DMODEL + d;
    float s = 0.f;
#pragma unroll 8
    for (int t = 0; t < CHLEN; t++) s += up[(size_t)t * DMODEL];
    g_cs[((size_t)b * NCHUNK + c) * DMODEL + d] = s;
}

__global__ void spectral_kernel(const float* __restrict__ u)
{
    const int b = blockIdx.x >> 4;
    const int c = blockIdx.x & 15;
    const int d = threadIdx.x;
    float acc = 0.f;
    for (int cc = 0; cc < c; cc++) acc += g_cs[((size_t)b * NCHUNK + cc) * DMODEL + d];
    const float* up = u + ((size_t)b * LL + (size_t)c * CHLEN) * DMODEL + d;
    float* op = g_udt + ((size_t)b * LL + (size_t)c * CHLEN) * HIN + d;
    for (int t = 0; t < CHLEN; t++) {
        float v = up[(size_t)t * DMODEL];
        acc += v;
        int tt = c * CHLEN + t + 1;
        op[(size_t)t * HIN] = v - acc / (float)tt;
    }
}

__global__ void copydt_kernel()
{
    int idx = blockIdx.x * 256 + threadIdx.x;
    if (idx >= NROWS * 32) return;
    int r = idx >> 5, k = idx & 31;
    g_udt[(size_t)r * HIN + 1024 + k] = g_zxbcdt[(size_t)r * DINPROJ + 2304 + k];
}

// ---------------- top-k + dt/softplus/decay ----------------
__global__ void dtprep_kernel(const float* __restrict__ dt_bias,
                              const float* __restrict__ gamma,
                              const float* __restrict__ A_log)
{
    const int r = blockIdx.x * 128 + threadIdx.x;
    if (r >= NROWS) return;
    const float* hr = g_hb + (size_t)r * HOUT;
    float h[28];
#pragma unroll
    for (int i = 0; i < 28; i++) h[i] = hr[i];
    const float* dtall = g_zxbcdt + (size_t)r * DINPROJ + 2304;
    const float bias = dt_bias[0];

#pragma unroll
    for (int i = 0; i < 28; i++) {
        int rank = 0;
#pragma unroll
        for (int j = 0; j < 28; j++)
            rank += (h[j] > h[i]) || (h[j] == h[i] && j < i);
        if (rank < 12) {
            float dtv = dtall[i] + bias + gamma[rank] * hr[28 + rank];
            float sp = (dtv > 20.f) ? dtv : log1pf(expf(dtv));
            float dec = expf(-expf(A_log[rank]) * sp);
            g_dt[(size_t)r * 16 + rank] = sp;
            g_decay[(size_t)r * 16 + rank] = dec;
        }
    }
#pragma unroll
    for (int k = 12; k < 16; k++) {
        float dtv = dtall[k + 16] + bias;
        float sp = (dtv > 20.f) ? dtv : log1pf(expf(dtv));
        float dec = expf(-expf(A_log[k]) * sp);
        g_dt[(size_t)r * 16 + k] = sp;
        g_decay[(size_t)r * 16 + k] = dec;
    }
}

// ---------------- causal depthwise conv + SiLU (float4 over channels) ----------------
__global__ void conv_kernel(const float* __restrict__ cw, const float* __restrict__ cb)
{
    int idx = blockIdx.x * 256 + threadIdx.x;               // NROWS * CONVDIM/4 work items
    if (idx >= NROWS * (CONVDIM / 4)) return;
    const int c4 = (idx % (CONVDIM / 4)) * 4;
    const int r = idx / (CONVDIM / 4);
    const int t = r & (LL - 1);
    const float* base = g_zxbcdt + (size_t)r * DINPROJ + 1024 + c4;
    float4 x0 = *(const float4*)base;
    float4 x1 = (t >= 1) ? *(const float4*)(base - DINPROJ)     : make_float4(0,0,0,0);
    float4 x2 = (t >= 2) ? *(const float4*)(base - 2 * DINPROJ) : make_float4(0,0,0,0);
    float4 x3 = (t >= 3) ? *(const float4*)(base - 3 * DINPROJ) : make_float4(0,0,0,0);
    float4 bias = *(const float4*)(cb + c4);
    float4 outv;
#pragma unroll
    for (int j = 0; j < 4; j++) {
        const float* w = cw + (c4 + j) * 4;
        float a0 = j==0?x0.x:j==1?x0.y:j==2?x0.z:x0.w;
        float a1 = j==0?x1.x:j==1?x1.y:j==2?x1.z:x1.w;
        float a2 = j==0?x2.x:j==1?x2.y:j==2?x2.z:x2.w;
        float a3 = j==0?x3.x:j==1?x3.y:j==2?x3.z:x3.w;
        float bj = j==0?bias.x:j==1?bias.y:j==2?bias.z:bias.w;
        float acc = bj + w[3]*a0 + w[2]*a1 + w[1]*a2 + w[0]*a3;
        float sig = 1.f / (1.f + expf(-acc));
        float res = acc * sig;
        if (j==0) outv.x = res; else if (j==1) outv.y = res;
        else if (j==2) outv.z = res; else outv.w = res;
    }
    *(float4*)(g_conv + (size_t)r * CONVDIM + c4) = outv;
}

// ---------------- selective scan: 2 CTAs per (b,h) split over n ----------------
__global__ __launch_bounds__(128, 1) void scan_kernel(const float* __restrict__ Dparam)
{
    const int b  = blockIdx.x >> 5;
    const int h  = (blockIdx.x >> 1) & 15;
    const int nh = blockIdx.x & 1;
    const int tid = threadIdx.x;
    const int q = tid & 1;
    const int p = tid >> 1;
    const int nbase = q * 32;

    __shared__ __align__(16) float sB[2][64];
    __shared__ __align__(16) float sC[2][64];
    __shared__ __align__(16) float sx[2][64];
    __shared__ float ssc[2][2];

    float s[32];
#pragma unroll
    for (int i = 0; i < 32; i++) s[i] = 0.f;

    const float Dh = Dparam[h];
    const float* cbase = g_conv + (size_t)b * LL * CONVDIM;
    const size_t rbase = (size_t)b * LL;
    float* dst = nh ? g_y2 : g_y;
    const int noff = 1024 + nh * 64;

    {
        const float* row = cbase;
        if (tid < 64) {
            sB[0][tid] = row[noff + tid];
            sC[0][tid] = row[noff + 128 + tid];
            sx[0][tid] = row[h * 64 + tid];
        }
        if (tid == 0) ssc[0][0] = g_dt[rbase * 16 + h];
        if (tid == 1) ssc[0][1] = g_decay[rbase * 16 + h];
    }
    __syncthreads();

    for (int t = 0; t < LL; t++) {
        const int cur = t & 1, nxt = cur ^ 1;
        const bool hasNext = (t + 1 < LL);
        float pB = 0.f, pC = 0.f, px = 0.f, psc = 0.f;
        if (hasNext) {
            const float* row = cbase + (size_t)(t + 1) * CONVDIM;
            if (tid < 64) {
                pB = row[noff + tid];
                pC = row[noff + 128 + tid];
                px = row[h * 64 + tid];
            }
            if (tid == 0) psc = g_dt[(rbase + t + 1) * 16 + h];
            if (tid == 1) psc = g_decay[(rbase + t + 1) * 16 + h];
        }
        const float dtv = ssc[cur][0];
        const float dec = ssc[cur][1];
        const float xv = sx[cur][p];
        const float coef = dtv * xv;

        float yv0 = 0.f, yv1 = 0.f;
        const float4* B4 = (const float4*)&sB[cur][nbase];
        const float4* C4 = (const float4*)&sC[cur][nbase];
#pragma unroll
        for (int g = 0; g < 8; g++) {
            float4 bb = B4[g];
            float4 cc = C4[g];
            s[4 * g + 0] = fmaf(s[4 * g + 0], dec, coef * bb.x);
            s[4 * g + 1] = fmaf(s[4 * g + 1], dec, coef * bb.y);
            s[4 * g + 2] = fmaf(s[4 * g + 2], dec, coef * bb.z);
            s[4 * g + 3] = fmaf(s[4 * g + 3], dec, coef * bb.w);
            yv0 = fmaf(s[4 * g + 0], cc.x, yv0);
            yv1 = fmaf(s[4 * g + 1], cc.y, yv1);
            yv0 = fmaf(s[4 * g + 2], cc.z, yv0);
            yv1 = fmaf(s[4 * g + 3], cc.w, yv1);
        }
        float yv = yv0 + yv1;
        yv += __shfl_xor_sync(0xffffffffu, yv, 1);
        if (q == 0)
            dst[(rbase + t) * DMODEL + h * 64 + p] = yv + (nh == 0 ? Dh * xv : 0.f);

        if (hasNext) {
            if (tid < 64) {
                sB[nxt][tid] = pB;
                sC[nxt][tid] = pC;
                sx[nxt][tid] = px;
            }
            if (tid < 2) ssc[nxt][tid] = psc;
        }
        __syncthreads();
    }
}

// ---------------- gated RMS norm (sum partials) -> split-bf16 ----------------
__global__ __launch_bounds__(256) void rmsnorm_kernel(const float* __restrict__ norm_w,
                                                      __nv_bfloat16* __restrict__ outbig)
{
    const int r = blockIdx.x;
    const int tid = threadIdx.x;
    const float* y0 = g_y  + (size_t)r * DMODEL;
    const float* y1 = g_y2 + (size_t)r * DMODEL;
    const float* zr = g_zxbcdt + (size_t)r * DINPROJ;

    float yz[4];
    float ss = 0.f;
#pragma unroll
    for (int i = 0; i < 4; i++) {
        int d = tid + 256 * i;
        float zv = zr[d];
        float v = (y0[d] + y1[d]) * (zv / (1.f + expf(-zv)));
        yz[i] = v;
        ss += v * v;
    }
#pragma unroll
    for (int o = 16; o > 0; o >>= 1) ss += __shfl_xor_sync(0xffffffffu, ss, o);
    __shared__ float red[8];
    __shared__ float sscale;
    if ((tid & 31) == 0) red[tid >> 5] = ss;
    __syncthreads();
    if (tid == 0) {
        float tot = 0.f;
#pragma unroll
        for (int w = 0; w < 8; w++) tot += red[w];
        sscale = rsqrtf(tot * (1.f / (float)DMODEL) + 1e-5f);
    }
    __syncthreads();
    const float scale = sscale;
    __nv_bfloat16* ob = outbig + (size_t)r * KSPLIT;
#pragma unroll
    for (int i = 0; i < 4; i++) {
        int d = tid + 256 * i;
        float v = yz[i] * scale * norm_w[d];
        __nv_bfloat16 hi = __float2bfloat16(v);
        __nv_bfloat16 lo = __float2bfloat16(v - __bfloat162float(hi));
        ob[d] = hi; ob[1024 + d] = hi; ob[2048 + d] = lo;
    }
}

// ---------------- launch ----------------
extern "C" void kernel_launch(void* const* d_in, const int* in_sizes, int n_in,
                              void* d_out, int out_size)
{
    const float* u          = (const float*)d_in[0];
    const float* in_proj_w  = (const float*)d_in[1];
    const float* h_proj_w   = (const float*)d_in[2];
    const float* conv_w     = (const float*)d_in[3];
    const float* conv_b     = (const float*)d_in[4];
    const float* dt_bias    = (const float*)d_in[5];
    const float* gamma      = (const float*)d_in[6];
    const float* A_log      = (const float*)d_in[7];
    const float* Dp         = (const float*)d_in[8];
    const float* norm_w     = (const float*)d_in[9];
    const float* out_proj_w = (const float*)d_in[10];
    float* out = (float*)d_out;

    void* p;
    cudaGetSymbolAddress(&p, g_zxbcdt); float* zx  = (float*)p;
    cudaGetSymbolAddress(&p, g_udt);    float* udt = (float*)p;
    cudaGetSymbolAddress(&p, g_hb);     float* hb  = (float*)p;
    cudaGetSymbolAddress(&p, g_abig);   __nv_bfloat16* abig = (__nv_bfloat16*)p;
    cudaGetSymbolAddress(&p, g_wbig);   __nv_bfloat16* wbig = (__nv_bfloat16*)p;

    cudaFuncSetAttribute(bgemm3, cudaFuncAttributeMaxDynamicSharedMemorySize, TGSMEM);

    // 1) split + tensor-core in_proj
    split3_kernel<<<NROWS, 256>>>(u, abig, NROWS, 0);
    split3_kernel<<<DINPROJ, 256>>>(in_proj_w, wbig, DINPROJ, 1);
    {
        dim3 grid((DINPROJ + 127) / 128, NROWS / 128);
        bgemm3<<<grid, 256, TGSMEM>>>(abig, wbig, zx, NROWS, DINPROJ, KSPLIT);
    }
    // 2-3) spectral residual
    chunksum_kernel<<<BB * NCHUNK, DMODEL>>>(u);
    spectral_kernel<<<BB * NCHUNK, DMODEL>>>(u);
    // 4) dt columns
    copydt_kernel<<<(NROWS * 32 + 255) / 256, 256>>>();
    // 5) h_proj (fp32)
    {
        dim3 grid(1, NROWS / 64);
        sgemm64<<<grid, 256>>>(udt, h_proj_w, hb, NROWS, HOUT, HIN);
    }
    // 6) top-k + dt/decay
    dtprep_kernel<<<(NROWS + 127) / 128, 128>>>(dt_bias, gamma, A_log);
    // 7) conv + silu
    conv_kernel<<<(NROWS * (CONVDIM / 4) + 255) / 256, 256>>>(conv_w, conv_b);
    // 8) scan
    scan_kernel<<<BB * 16 * 2, 128>>>(Dp);
    // 9) rmsnorm -> split bf16
    rmsnorm_kernel<<<NROWS, 256>>>(norm_w, abig);
    // 10) out_proj
    split3_kernel<<<DMODEL, 256>>>(out_proj_w, wbig, DMODEL, 1);
    {
        dim3 grid(DMODEL / 128, NROWS / 128);
        bgemm3<<<grid, 256, TGSMEM>>>(abig, wbig, out, NROWS, DMODEL, KSPLIT);
    }
    (void)in_sizes; (void)n_in; (void)out_size;
}

// round 7
// speedup vs baseline: 1.1845x; 1.1845x over previous
#include <cuda_runtime.h>
#include <cuda_fp16.h>
#include <stdint.h>
#include <math.h>

#define BB 4
#define LL 2048
#define DMODEL 1024
#define DINPROJ 2336
#define HIN 1056
#define HOUT 40
#define CONVDIM 1280
#define NROWS (BB*LL)          // 8192
#define NCHUNK 16
#define CHLEN 128
#define KSPLIT 2048            // 2 * DMODEL (fp16 hi/lo split concatenated K)

// ---------------- scratch ----------------
__device__ float g_zxbcdt[NROWS * DINPROJ];
__device__ float g_udt[NROWS * HIN];
__device__ float g_cs[BB * NCHUNK * DMODEL];
__device__ float g_hb[NROWS * HOUT];
__device__ float g_dt[NROWS * 16];
__device__ float g_decay[NROWS * 16];
__device__ float g_conv[NROWS * CONVDIM];
__device__ float g_y[NROWS * DMODEL];    // scan partial (n-half 0, incl. D*x)
__device__ float g_y2[NROWS * DMODEL];   // scan partial (n-half 1)
__device__ __half g_abig[(size_t)NROWS * KSPLIT];    // [Ah|Al]
__device__ __half g_wbig[(size_t)DINPROJ * KSPLIT];  // [Wh|Wh]

// ---------------- ptx helpers ----------------
__device__ __forceinline__ void cpa16(uint32_t dst, const void* src, bool v) {
    asm volatile("cp.async.cg.shared.global [%0], [%1], 16, %2;\n"
                 :: "r"(dst), "l"(src), "r"(v ? 16 : 0));
}
#define CP_COMMIT() asm volatile("cp.async.commit_group;\n")
#define CP_WAIT0()  asm volatile("cp.async.wait_group 0;\n")
__device__ __forceinline__ void ldsm4(uint32_t addr, unsigned& a0, unsigned& a1,
                                      unsigned& a2, unsigned& a3) {
    asm volatile("ldmatrix.sync.aligned.m8n8.x4.shared.b16 {%0,%1,%2,%3}, [%4];\n"
                 : "=r"(a0), "=r"(a1), "=r"(a2), "=r"(a3) : "r"(addr));
}

// ---------------- fp16 split conversion ----------------
// mode 0 (activations): [hi | lo]    mode 1 (weights): [hi | hi]
__global__ void split2_kernel(const float* __restrict__ src, __half* __restrict__ dst,
                              int rows, int mode)
{
    int idx = blockIdx.x * 256 + threadIdx.x;
    if (idx >= rows * 256) return;
    int r = idx >> 8;
    int c4 = (idx & 255) * 4;
    float4 v = *(const float4*)(src + (size_t)r * DMODEL + c4);
    __half h0 = __float2half(v.x), h1 = __float2half(v.y);
    __half h2 = __float2half(v.z), h3 = __float2half(v.w);
    __half2 hA = __halves2half2(h0, h1), hB = __halves2half2(h2, h3);
    __half2* d0 = (__half2*)(dst + (size_t)r * KSPLIT + c4);
    __half2* d1 = (__half2*)(dst + (size_t)r * KSPLIT + 1024 + c4);
    d0[0] = hA; d0[1] = hB;
    if (mode == 0) {
        __half l0 = __float2half(v.x - __half2float(h0));
        __half l1 = __float2half(v.y - __half2float(h1));
        __half l2 = __float2half(v.z - __half2float(h2));
        __half l3 = __float2half(v.w - __half2float(h3));
        d1[0] = __halves2half2(l0, l1); d1[1] = __halves2half2(l2, l3);
    } else {
        d1[0] = hA; d1[1] = hB;
    }
}

// ---------------- fp16 tensor-core GEMM, ldmatrix + cp.async 2-stage ----------------
// C[M,N] = A[M,K] * W[N,K]^T.  CTA 128x128, BK=32, 8 warps (2x4), warp 64x32.
__global__ __launch_bounds__(256) void bgemm_tn(
    const __half* __restrict__ A, const __half* __restrict__ W,
    float* __restrict__ C, int M, int N, int K)
{
    __shared__ __align__(16) __half As[2][128][40];  // 80B rows, LDSM conflict-free
    __shared__ __align__(16) __half Ws[2][128][40];
    const int bm = blockIdx.y * 128;
    const int bn = blockIdx.x * 128;
    const int tid = threadIdx.x;
    const int warp = tid >> 5;
    const int lane = tid & 31;
    const int wm = (warp >> 2) * 64;
    const int wn = (warp & 3) * 32;
    const int lq = lane >> 2;
    const int ls = lane & 3;

    const int r0 = tid >> 2;          // 0..63
    const int c0 = tid & 3;           // 16B chunk (8 fp16)

    float acc[4][4][4];
#pragma unroll
    for (int i = 0; i < 4; i++)
#pragma unroll
        for (int j = 0; j < 4; j++)
#pragma unroll
            for (int q = 0; q < 4; q++) acc[i][j][q] = 0.f;

    const __half* Ap0 = A + (size_t)(bm + r0) * K + c0 * 8;
    const __half* Ap1 = Ap0 + (size_t)64 * K;
    const bool wv0 = (bn + r0) < N;
    const bool wv1 = (bn + r0 + 64) < N;
    const __half* Wp0 = W + (size_t)(bn + r0) * K + c0 * 8;
    const __half* Wp1 = Wp0 + (size_t)64 * K;

    uint32_t sa0[2], sa1[2], sw0[2], sw1[2];
#pragma unroll
    for (int s = 0; s < 2; s++) {
        sa0[s] = (uint32_t)__cvta_generic_to_shared(&As[s][r0][c0 * 8]);
        sa1[s] = (uint32_t)__cvta_generic_to_shared(&As[s][r0 + 64][c0 * 8]);
        sw0[s] = (uint32_t)__cvta_generic_to_shared(&Ws[s][r0][c0 * 8]);
        sw1[s] = (uint32_t)__cvta_generic_to_shared(&Ws[s][r0 + 64][c0 * 8]);
    }
    // ldmatrix source addressing pattern
    const int arow = lane & 15;
    const int acol = (lane >> 4) * 8;
    const int brow = (lane & 7) + ((lane >> 4) << 3);
    const int bcol = ((lane >> 3) & 1) * 8;

    const int KT = K >> 5;  // K/32 tiles

    // prologue: stage 0
    cpa16(sa0[0], Ap0, true);
    cpa16(sa1[0], Ap1, true);
    cpa16(sw0[0], Wp0, wv0);
    cpa16(sw1[0], Wp1, wv1);
    CP_COMMIT();

    for (int it = 0; it < KT; it++) {
        CP_WAIT0();
        __syncthreads();
        // issue next stage
        const int nk = (it + 1) * 32;
        const int ns = (it + 1) & 1;
        if (nk < K) {
            cpa16(sa0[ns], Ap0 + nk, true);
            cpa16(sa1[ns], Ap1 + nk, true);
            cpa16(sw0[ns], Wp0 + nk, wv0);
            cpa16(sw1[ns], Wp1 + nk, wv1);
        }
        CP_COMMIT();
        const int s = it & 1;
#pragma unroll
        for (int ks = 0; ks < 2; ks++) {
            const int kk = ks * 16;
            unsigned a[4][4], b[2][4];
#pragma unroll
            for (int i = 0; i < 4; i++) {
                uint32_t ad = (uint32_t)__cvta_generic_to_shared(
                    &As[s][wm + i * 16 + arow][kk + acol]);
                ldsm4(ad, a[i][0], a[i][1], a[i][2], a[i][3]);
            }
#pragma unroll
            for (int jp = 0; jp < 2; jp++) {
                uint32_t bd = (uint32_t)__cvta_generic_to_shared(
                    &Ws[s][wn + jp * 16 + brow][kk + bcol]);
                ldsm4(bd, b[jp][0], b[jp][1], b[jp][2], b[jp][3]);
            }
#pragma unroll
            for (int i = 0; i < 4; i++)
#pragma unroll
                for (int j = 0; j < 4; j++) {
                    const unsigned b0 = b[j >> 1][(j & 1) * 2];
                    const unsigned b1 = b[j >> 1][(j & 1) * 2 + 1];
                    asm volatile(
                        "mma.sync.aligned.m16n8k16.row.col.f32.f16.f16.f32 "
                        "{%0,%1,%2,%3}, {%4,%5,%6,%7}, {%8,%9}, {%0,%1,%2,%3};\n"
                        : "+f"(acc[i][j][0]), "+f"(acc[i][j][1]),
                          "+f"(acc[i][j][2]), "+f"(acc[i][j][3])
                        : "r"(a[i][0]), "r"(a[i][1]), "r"(a[i][2]), "r"(a[i][3]),
                          "r"(b0), "r"(b1));
                }
        }
        __syncthreads();
    }

#pragma unroll
    for (int i = 0; i < 4; i++) {
        const int r = bm + wm + i * 16 + lq;
#pragma unroll
        for (int j = 0; j < 4; j++) {
            const int n = bn + wn + j * 8 + 2 * ls;
            if (n < N) {
                *(float2*)&C[(size_t)r * N + n]       = make_float2(acc[i][j][0], acc[i][j][1]);
                *(float2*)&C[(size_t)(r + 8) * N + n] = make_float2(acc[i][j][2], acc[i][j][3]);
            }
        }
    }
}

// ---------------- fp32 h_proj GEMM: BM=64, BN=64 (N=40 guarded), BK=16 ----------------
__global__ __launch_bounds__(256) void sgemm64(
    const float* __restrict__ A, const float* __restrict__ W,
    float* __restrict__ C, int M, int N, int K)
{
    __shared__ __align__(16) float As[16][64];
    __shared__ __align__(16) float Bs[16][64];
    const int bm = blockIdx.y * 64;
    const int tid = threadIdx.x;
    const int lr = tid >> 2;
    const int lc = (tid & 3) << 2;
    const int tr = tid >> 4;
    const int tc = tid & 15;

    float acc[4][4];
#pragma unroll
    for (int i = 0; i < 4; i++)
#pragma unroll
        for (int j = 0; j < 4; j++) acc[i][j] = 0.f;

    const float* Aptr = A + (size_t)(bm + lr) * K + lc;
    const float* Wptr = W + (size_t)lr * K + lc;
    const bool wvalid = lr < N;

    for (int k0 = 0; k0 < K; k0 += 16) {
        float4 av = *(const float4*)(Aptr + k0);
        float4 bv = wvalid ? *(const float4*)(Wptr + k0) : make_float4(0.f, 0.f, 0.f, 0.f);
        As[lc + 0][lr] = av.x; As[lc + 1][lr] = av.y; As[lc + 2][lr] = av.z; As[lc + 3][lr] = av.w;
        Bs[lc + 0][lr] = bv.x; Bs[lc + 1][lr] = bv.y; Bs[lc + 2][lr] = bv.z; Bs[lc + 3][lr] = bv.w;
        __syncthreads();
#pragma unroll
        for (int k = 0; k < 16; k++) {
            float ra[4], rb[4];
#pragma unroll
            for (int i = 0; i < 4; i++) ra[i] = As[k][tr + 16 * i];
#pragma unroll
            for (int j = 0; j < 4; j++) rb[j] = Bs[k][tc + 16 * j];
#pragma unroll
            for (int i = 0; i < 4; i++)
#pragma unroll
                for (int j = 0; j < 4; j++) acc[i][j] = fmaf(ra[i], rb[j], acc[i][j]);
        }
        __syncthreads();
    }
#pragma unroll
    for (int i = 0; i < 4; i++) {
        const int m = bm + tr + 16 * i;
#pragma unroll
        for (int j = 0; j < 4; j++) {
            const int n = tc + 16 * j;
            if (n < N) C[(size_t)m * N + n] = acc[i][j];
        }
    }
}

// ---------------- spectral residual ----------------
__global__ void chunksum_kernel(const float* __restrict__ u)
{
    const int b = blockIdx.x >> 4;
    const int c = blockIdx.x & 15;
    const int d = threadIdx.x;
    const float* up = u + ((size_t)b * LL + (size_t)c * CHLEN) * DMODEL + d;
    float s = 0.f;
#pragma unroll 8
    for (int t = 0; t < CHLEN; t++) s += up[(size_t)t * DMODEL];
    g_cs[((size_t)b * NCHUNK + c) * DMODEL + d] = s;
}

__global__ void spectral_kernel(const float* __restrict__ u)
{
    const int b = blockIdx.x >> 4;
    const int c = blockIdx.x & 15;
    const int d = threadIdx.x;
    float acc = 0.f;
    for (int cc = 0; cc < c; cc++) acc += g_cs[((size_t)b * NCHUNK + cc) * DMODEL + d];
    const float* up = u + ((size_t)b * LL + (size_t)c * CHLEN) * DMODEL + d;
    float* op = g_udt + ((size_t)b * LL + (size_t)c * CHLEN) * HIN + d;
    for (int t = 0; t < CHLEN; t++) {
        float v = up[(size_t)t * DMODEL];
        acc += v;
        int tt = c * CHLEN + t + 1;
        op[(size_t)t * HIN] = v - acc / (float)tt;
    }
}

__global__ void copydt_kernel()
{
    int idx = blockIdx.x * 256 + threadIdx.x;
    if (idx >= NROWS * 32) return;
    int r = idx >> 5, k = idx & 31;
    g_udt[(size_t)r * HIN + 1024 + k] = g_zxbcdt[(size_t)r * DINPROJ + 2304 + k];
}

// ---------------- top-k + dt/softplus/decay ----------------
__global__ void dtprep_kernel(const float* __restrict__ dt_bias,
                              const float* __restrict__ gamma,
                              const float* __restrict__ A_log)
{
    const int r = blockIdx.x * 128 + threadIdx.x;
    if (r >= NROWS) return;
    const float* hr = g_hb + (size_t)r * HOUT;
    float h[28];
#pragma unroll
    for (int i = 0; i < 28; i++) h[i] = hr[i];
    const float* dtall = g_zxbcdt + (size_t)r * DINPROJ + 2304;
    const float bias = dt_bias[0];

#pragma unroll
    for (int i = 0; i < 28; i++) {
        int rank = 0;
#pragma unroll
        for (int j = 0; j < 28; j++)
            rank += (h[j] > h[i]) || (h[j] == h[i] && j < i);
        if (rank < 12) {
            float dtv = dtall[i] + bias + gamma[rank] * hr[28 + rank];
            float sp = (dtv > 20.f) ? dtv : log1pf(expf(dtv));
            float dec = expf(-expf(A_log[rank]) * sp);
            g_dt[(size_t)r * 16 + rank] = sp;
            g_decay[(size_t)r * 16 + rank] = dec;
        }
    }
#pragma unroll
    for (int k = 12; k < 16; k++) {
        float dtv = dtall[k + 16] + bias;
        float sp = (dtv > 20.f) ? dtv : log1pf(expf(dtv));
        float dec = expf(-expf(A_log[k]) * sp);
        g_dt[(size_t)r * 16 + k] = sp;
        g_decay[(size_t)r * 16 + k] = dec;
    }
}

// ---------------- causal depthwise conv + SiLU (float4 over channels) ----------------
__global__ void conv_kernel(const float* __restrict__ cw, const float* __restrict__ cb)
{
    int idx = blockIdx.x * 256 + threadIdx.x;
    if (idx >= NROWS * (CONVDIM / 4)) return;
    const int c4 = (idx % (CONVDIM / 4)) * 4;
    const int r = idx / (CONVDIM / 4);
    const int t = r & (LL - 1);
    const float* base = g_zxbcdt + (size_t)r * DINPROJ + 1024 + c4;
    float4 x0 = *(const float4*)base;
    float4 x1 = (t >= 1) ? *(const float4*)(base - DINPROJ)     : make_float4(0,0,0,0);
    float4 x2 = (t >= 2) ? *(const float4*)(base - 2 * DINPROJ) : make_float4(0,0,0,0);
    float4 x3 = (t >= 3) ? *(const float4*)(base - 3 * DINPROJ) : make_float4(0,0,0,0);
    float4 bias = *(const float4*)(cb + c4);
    float4 outv;
#pragma unroll
    for (int j = 0; j < 4; j++) {
        const float* w = cw + (c4 + j) * 4;
        float a0 = j==0?x0.x:j==1?x0.y:j==2?x0.z:x0.w;
        float a1 = j==0?x1.x:j==1?x1.y:j==2?x1.z:x1.w;
        float a2 = j==0?x2.x:j==1?x2.y:j==2?x2.z:x2.w;
        float a3 = j==0?x3.x:j==1?x3.y:j==2?x3.z:x3.w;
        float bj = j==0?bias.x:j==1?bias.y:j==2?bias.z:bias.w;
        float acc = bj + w[3]*a0 + w[2]*a1 + w[1]*a2 + w[0]*a3;
        float sig = 1.f / (1.f + expf(-acc));
        float res = acc * sig;
        if (j==0) outv.x = res; else if (j==1) outv.y = res;
        else if (j==2) outv.z = res; else outv.w = res;
    }
    *(float4*)(g_conv + (size_t)r * CONVDIM + c4) = outv;
}

// ---------------- selective scan: 2 CTAs per (b,h) split over n ----------------
__global__ __launch_bounds__(128, 1) void scan_kernel(const float* __restrict__ Dparam)
{
    const int b  = blockIdx.x >> 5;
    const int h  = (blockIdx.x >> 1) & 15;
    const int nh = blockIdx.x & 1;
    const int tid = threadIdx.x;
    const int q = tid & 1;
    const int p = tid >> 1;
    const int nbase = q * 32;

    __shared__ __align__(16) float sB[2][64];
    __shared__ __align__(16) float sC[2][64];
    __shared__ __align__(16) float sx[2][64];
    __shared__ float ssc[2][2];

    float s[32];
#pragma unroll
    for (int i = 0; i < 32; i++) s[i] = 0.f;

    const float Dh = Dparam[h];
    const float* cbase = g_conv + (size_t)b * LL * CONVDIM;
    const size_t rbase = (size_t)b * LL;
    float* dst = nh ? g_y2 : g_y;
    const int noff = 1024 + nh * 64;

    {
        const float* row = cbase;
        if (tid < 64) {
            sB[0][tid] = row[noff + tid];
            sC[0][tid] = row[noff + 128 + tid];
            sx[0][tid] = row[h * 64 + tid];
        }
        if (tid == 0) ssc[0][0] = g_dt[rbase * 16 + h];
        if (tid == 1) ssc[0][1] = g_decay[rbase * 16 + h];
    }
    __syncthreads();

    for (int t = 0; t < LL; t++) {
        const int cur = t & 1, nxt = cur ^ 1;
        const bool hasNext = (t + 1 < LL);
        float pB = 0.f, pC = 0.f, px = 0.f, psc = 0.f;
        if (hasNext) {
            const float* row = cbase + (size_t)(t + 1) * CONVDIM;
            if (tid < 64) {
                pB = row[noff + tid];
                pC = row[noff + 128 + tid];
                px = row[h * 64 + tid];
            }
            if (tid == 0) psc = g_dt[(rbase + t + 1) * 16 + h];
            if (tid == 1) psc = g_decay[(rbase + t + 1) * 16 + h];
        }
        const float dtv = ssc[cur][0];
        const float dec = ssc[cur][1];
        const float xv = sx[cur][p];
        const float coef = dtv * xv;

        float yv0 = 0.f, yv1 = 0.f;
        const float4* B4 = (const float4*)&sB[cur][nbase];
        const float4* C4 = (const float4*)&sC[cur][nbase];
#pragma unroll
        for (int g = 0; g < 8; g++) {
            float4 bb = B4[g];
            float4 cc = C4[g];
            s[4 * g + 0] = fmaf(s[4 * g + 0], dec, coef * bb.x);
            s[4 * g + 1] = fmaf(s[4 * g + 1], dec, coef * bb.y);
            s[4 * g + 2] = fmaf(s[4 * g + 2], dec, coef * bb.z);
            s[4 * g + 3] = fmaf(s[4 * g + 3], dec, coef * bb.w);
            yv0 = fmaf(s[4 * g + 0], cc.x, yv0);
            yv1 = fmaf(s[4 * g + 1], cc.y, yv1);
            yv0 = fmaf(s[4 * g + 2], cc.z, yv0);
            yv1 = fmaf(s[4 * g + 3], cc.w, yv1);
        }
        float yv = yv0 + yv1;
        yv += __shfl_xor_sync(0xffffffffu, yv, 1);
        if (q == 0)
            dst[(rbase + t) * DMODEL + h * 64 + p] = yv + (nh == 0 ? Dh * xv : 0.f);

        if (hasNext) {
            if (tid < 64) {
                sB[nxt][tid] = pB;
                sC[nxt][tid] = pC;
                sx[nxt][tid] = px;
            }
            if (tid < 2) ssc[nxt][tid] = psc;
        }
        __syncthreads();
    }
}

// ---------------- gated RMS norm (sum partials) -> split-fp16 ----------------
__global__ __launch_bounds__(256) void rmsnorm_kernel(const float* __restrict__ norm_w,
                                                      __half* __restrict__ outbig)
{
    const int r = blockIdx.x;
    const int tid = threadIdx.x;
    const float* y0 = g_y  + (size_t)r * DMODEL;
    const float* y1 = g_y2 + (size_t)r * DMODEL;
    const float* zr = g_zxbcdt + (size_t)r * DINPROJ;

    float yz[4];
    float ss = 0.f;
#pragma unroll
    for (int i = 0; i < 4; i++) {
        int d = tid + 256 * i;
        float zv = zr[d];
        float v = (y0[d] + y1[d]) * (zv / (1.f + expf(-zv)));
        yz[i] = v;
        ss += v * v;
    }
#pragma unroll
    for (int o = 16; o > 0; o >>= 1) ss += __shfl_xor_sync(0xffffffffu, ss, o);
    __shared__ float red[8];
    __shared__ float sscale;
    if ((tid & 31) == 0) red[tid >> 5] = ss;
    __syncthreads();
    if (tid == 0) {
        float tot = 0.f;
#pragma unroll
        for (int w = 0; w < 8; w++) tot += red[w];
        sscale = rsqrtf(tot * (1.f / (float)DMODEL) + 1e-5f);
    }
    __syncthreads();
    const float scale = sscale;
    __half* ob = outbig + (size_t)r * KSPLIT;
#pragma unroll
    for (int i = 0; i < 4; i++) {
        int d = tid + 256 * i;
        float v = yz[i] * scale * norm_w[d];
        __half hi = __float2half(v);
        __half lo = __float2half(v - __half2float(hi));
        ob[d] = hi; ob[1024 + d] = lo;
    }
}

// ---------------- launch ----------------
extern "C" void kernel_launch(void* const* d_in, const int* in_sizes, int n_in,
                              void* d_out, int out_size)
{
    const float* u          = (const float*)d_in[0];
    const float* in_proj_w  = (const float*)d_in[1];
    const float* h_proj_w   = (const float*)d_in[2];
    const float* conv_w     = (const float*)d_in[3];
    const float* conv_b     = (const float*)d_in[4];
    const float* dt_bias    = (const float*)d_in[5];
    const float* gamma      = (const float*)d_in[6];
    const float* A_log      = (const float*)d_in[7];
    const float* Dp         = (const float*)d_in[8];
    const float* norm_w     = (const float*)d_in[9];
    const float* out_proj_w = (const float*)d_in[10];
    float* out = (float*)d_out;

    void* p;
    cudaGetSymbolAddress(&p, g_zxbcdt); float* zx  = (float*)p;
    cudaGetSymbolAddress(&p, g_udt);    float* udt = (float*)p;
    cudaGetSymbolAddress(&p, g_hb);     float* hb  = (float*)p;
    cudaGetSymbolAddress(&p, g_abig);   __half* abig = (__half*)p;
    cudaGetSymbolAddress(&p, g_wbig);   __half* wbig = (__half*)p;

    // 1) split + tensor-core in_proj (fp16 2-term split, K=2048)
    split2_kernel<<<NROWS, 256>>>(u, abig, NROWS, 0);
    split2_kernel<<<DINPROJ, 256>>>(in_proj_w, wbig, DINPROJ, 1);
    {
        dim3 grid((DINPROJ + 127) / 128, NROWS / 128);
        bgemm_tn<<<grid, 256>>>(abig, wbig, zx, NROWS, DINPROJ, KSPLIT);
    }
    // 2-3) spectral residual
    chunksum_kernel<<<BB * NCHUNK, DMODEL>>>(u);
    spectral_kernel<<<BB * NCHUNK, DMODEL>>>(u);
    // 4) dt columns
    copydt_kernel<<<(NROWS * 32 + 255) / 256, 256>>>();
    // 5) h_proj (fp32)
    {
        dim3 grid(1, NROWS / 64);
        sgemm64<<<grid, 256>>>(udt, h_proj_w, hb, NROWS, HOUT, HIN);
    }
    // 6) top-k + dt/decay
    dtprep_kernel<<<(NROWS + 127) / 128, 128>>>(dt_bias, gamma, A_log);
    // 7) conv + silu
    conv_kernel<<<(NROWS * (CONVDIM / 4) + 255) / 256, 256>>>(conv_w, conv_b);
    // 8) scan
    scan_kernel<<<BB * 16 * 2, 128>>>(Dp);
    // 9) rmsnorm -> split fp16
    rmsnorm_kernel<<<NROWS, 256>>>(norm_w, abig);
    // 10) out_proj
    split2_kernel<<<DMODEL, 256>>>(out_proj_w, wbig, DMODEL, 1);
    {
        dim3 grid(DMODEL / 128, NROWS / 128);
        bgemm_tn<<<grid, 256>>>(abig, wbig, out, NROWS, DMODEL, KSPLIT);
    }
    (void)in_sizes; (void)n_in; (void)out_size;
}